// round 1
// baseline (speedup 1.0000x reference)
#include <cuda_runtime.h>
#include <cstddef>

// Problem constants
#define BATCH 2
#define SEQ   2048
#define DM    768
#define NH    12
#define DHD   64
#define ATT_SCALE 0.125f   // 1/sqrt(64)

// Scratch (allocation-free rule: __device__ globals)
__device__ float g_q[BATCH * SEQ * DM];
__device__ float g_k[BATCH * SEQ * DM];
__device__ float g_v[BATCH * SEQ * DM];
__device__ float g_attn[BATCH * SEQ * DM];

// ---------------------------------------------------------------------------
// Reusable block GEMM: C_block[128 x 64] = A_block[128 x K] * B_block[K x 64]
//   A: row-major, K contiguous (lda stride between rows)
//   B: BTRANS=true  -> B[n*ldb + k]   (K contiguous per output col; "NT")
//      BTRANS=false -> B[k*ldb + n]   (N contiguous per k row;     "NN")
// 256 threads, per-thread 8x4 micro-tile, BK=16. K must be a multiple of 16.
// Caller passes A pre-offset to the block row, B pre-offset to the block col.
// ---------------------------------------------------------------------------
template <bool BTRANS>
__device__ __forceinline__ void gemm_block(
    const float* __restrict__ A, int lda,
    const float* __restrict__ Bm, int ldb,
    int K, float acc[8][4])
{
    __shared__ float As[16][128];
    __shared__ float Bs[16][64];

    const int tid = threadIdx.x;       // 0..255
    const int tx  = tid & 15;          // 0..15 -> 4 output cols
    const int ty  = tid >> 4;          // 0..15 -> 8 output rows

    for (int k0 = 0; k0 < K; k0 += 16) {
        // Load A tile 128x16 (2 float4 per thread), store transposed As[k][m]
        #pragma unroll
        for (int t = 0; t < 2; t++) {
            int i = tid + t * 256;     // 0..511 float4 slots
            int r = i >> 2;            // row 0..127
            int c = (i & 3) * 4;       // k offset 0,4,8,12
            float4 v = *(const float4*)(A + (size_t)r * lda + k0 + c);
            As[c + 0][r] = v.x;
            As[c + 1][r] = v.y;
            As[c + 2][r] = v.z;
            As[c + 3][r] = v.w;
        }
        // Load B tile into Bs[k][n]
        if (BTRANS) {
            // B[n*ldb + k]: 64 n x 16 k = 256 float4, one per thread
            int n = tid >> 2;
            int c = (tid & 3) * 4;
            float4 v = *(const float4*)(Bm + (size_t)n * ldb + k0 + c);
            Bs[c + 0][n] = v.x;
            Bs[c + 1][n] = v.y;
            Bs[c + 2][n] = v.z;
            Bs[c + 3][n] = v.w;
        } else {
            // B[k*ldb + n]: 16 k x 64 n = 256 float4, one per thread
            int kk = tid >> 4;
            int n  = (tid & 15) * 4;
            float4 v = *(const float4*)(Bm + (size_t)(k0 + kk) * ldb + n);
            *(float4*)&Bs[kk][n] = v;
        }
        __syncthreads();

        #pragma unroll
        for (int kk = 0; kk < 16; kk++) {
            float a[8], b[4];
            *(float4*)&a[0] = *(const float4*)&As[kk][ty * 8];
            *(float4*)&a[4] = *(const float4*)&As[kk][ty * 8 + 4];
            *(float4*)&b[0] = *(const float4*)&Bs[kk][tx * 4];
            #pragma unroll
            for (int i = 0; i < 8; i++)
                #pragma unroll
                for (int j = 0; j < 4; j++)
                    acc[i][j] += a[i] * b[j];
        }
        __syncthreads();
    }
}

// ---------------------------------------------------------------------------
// Projection: Y[M=4096, N=768] = X[4096,768] @ W^T[768,768] + bias
// grid = (N/64=12, M/128=32), 256 threads
// ---------------------------------------------------------------------------
__global__ void proj_kernel(const float* __restrict__ X,
                            const float* __restrict__ W,
                            const float* __restrict__ bias,
                            float* __restrict__ Y)
{
    float acc[8][4] = {};
    const float* A  = X + (size_t)blockIdx.y * 128 * DM;
    const float* Bm = W + (size_t)blockIdx.x * 64 * DM;
    gemm_block<true>(A, DM, Bm, DM, DM, acc);

    const int tx = threadIdx.x & 15, ty = threadIdx.x >> 4;
    const int row0 = blockIdx.y * 128 + ty * 8;
    const int col0 = blockIdx.x * 64 + tx * 4;
    float4 bv = *(const float4*)&bias[col0];
    #pragma unroll
    for (int i = 0; i < 8; i++) {
        float4 v;
        v.x = acc[i][0] + bv.x;
        v.y = acc[i][1] + bv.y;
        v.z = acc[i][2] + bv.z;
        v.w = acc[i][3] + bv.w;
        *(float4*)&Y[(size_t)(row0 + i) * DM + col0] = v;
    }
}

// ---------------------------------------------------------------------------
// Scores: P[z, q, k] = (Q_z[q,:] . K_z[k,:]) * scale, masked
// grid = (S/64=32 key blocks, S/128=16 query blocks, B*H=24)
// ---------------------------------------------------------------------------
__global__ void scores_kernel(const int* __restrict__ mask,
                              float* __restrict__ P)
{
    const int z = blockIdx.z;
    const int b = z / NH, h = z % NH;
    float acc[8][4] = {};
    const float* A  = g_q + (size_t)b * SEQ * DM + h * DHD
                          + (size_t)blockIdx.y * 128 * DM;
    const float* Bm = g_k + (size_t)b * SEQ * DM + h * DHD
                          + (size_t)blockIdx.x * 64 * DM;
    gemm_block<true>(A, DM, Bm, DM, DHD, acc);

    const int tx = threadIdx.x & 15, ty = threadIdx.x >> 4;
    const int row0 = blockIdx.y * 128 + ty * 8;
    const int col0 = blockIdx.x * 64 + tx * 4;
    const int* mrow = mask + b * SEQ;
    int m0 = mrow[col0 + 0], m1 = mrow[col0 + 1];
    int m2 = mrow[col0 + 2], m3 = mrow[col0 + 3];
    float* C = P + (size_t)z * SEQ * SEQ;
    #pragma unroll
    for (int i = 0; i < 8; i++) {
        float4 v;
        v.x = (m0 == 0) ? -1e9f : acc[i][0] * ATT_SCALE;
        v.y = (m1 == 0) ? -1e9f : acc[i][1] * ATT_SCALE;
        v.z = (m2 == 0) ? -1e9f : acc[i][2] * ATT_SCALE;
        v.w = (m3 == 0) ? -1e9f : acc[i][3] * ATT_SCALE;
        *(float4*)&C[(size_t)(row0 + i) * SEQ + col0] = v;
    }
}

// ---------------------------------------------------------------------------
// Row softmax in place: one block per row of 2048, 256 threads x 8 elems
// ---------------------------------------------------------------------------
__global__ void softmax_kernel(float* __restrict__ P)
{
    float* row = P + (size_t)blockIdx.x * SEQ;
    const int tid = threadIdx.x;
    float v[8];
    *(float4*)&v[0] = *(const float4*)&row[tid * 8];
    *(float4*)&v[4] = *(const float4*)&row[tid * 8 + 4];

    __shared__ float warp_red[8];
    __shared__ float bcast;

    // max
    float m = v[0];
    #pragma unroll
    for (int i = 1; i < 8; i++) m = fmaxf(m, v[i]);
    #pragma unroll
    for (int o = 16; o > 0; o >>= 1) m = fmaxf(m, __shfl_xor_sync(0xffffffffu, m, o));
    if ((tid & 31) == 0) warp_red[tid >> 5] = m;
    __syncthreads();
    if (tid == 0) {
        float t = warp_red[0];
        #pragma unroll
        for (int i = 1; i < 8; i++) t = fmaxf(t, warp_red[i]);
        bcast = t;
    }
    __syncthreads();
    const float rmax = bcast;
    __syncthreads();

    // exp + sum
    float s = 0.f;
    #pragma unroll
    for (int i = 0; i < 8; i++) {
        v[i] = __expf(v[i] - rmax);
        s += v[i];
    }
    #pragma unroll
    for (int o = 16; o > 0; o >>= 1) s += __shfl_xor_sync(0xffffffffu, s, o);
    if ((tid & 31) == 0) warp_red[tid >> 5] = s;
    __syncthreads();
    if (tid == 0) {
        float t = 0.f;
        #pragma unroll
        for (int i = 0; i < 8; i++) t += warp_red[i];
        bcast = t;
    }
    __syncthreads();
    const float inv = 1.0f / bcast;

    #pragma unroll
    for (int i = 0; i < 8; i++) v[i] *= inv;
    *(float4*)&row[tid * 8]     = *(float4*)&v[0];
    *(float4*)&row[tid * 8 + 4] = *(float4*)&v[4];
}

// ---------------------------------------------------------------------------
// PV: attn[b, q, h*64 + d] = sum_k P[z,q,k] * V[b,k,h*64+d]
// grid = (1, S/128=16, 24)
// ---------------------------------------------------------------------------
__global__ void pv_kernel(const float* __restrict__ P)
{
    const int z = blockIdx.z;
    const int b = z / NH, h = z % NH;
    float acc[8][4] = {};
    const float* A  = P + (size_t)z * SEQ * SEQ + (size_t)blockIdx.y * 128 * SEQ;
    const float* Bm = g_v + (size_t)b * SEQ * DM + h * DHD;   // NN form
    gemm_block<false>(A, SEQ, Bm, DM, SEQ, acc);

    const int tx = threadIdx.x & 15, ty = threadIdx.x >> 4;
    float* C = g_attn + (size_t)b * SEQ * DM + h * DHD
                      + (size_t)blockIdx.y * 128 * DM;
    #pragma unroll
    for (int i = 0; i < 8; i++) {
        float4 v;
        v.x = acc[i][0]; v.y = acc[i][1]; v.z = acc[i][2]; v.w = acc[i][3];
        *(float4*)&C[(size_t)(ty * 8 + i) * DM + tx * 4] = v;
    }
}

// ---------------------------------------------------------------------------
extern "C" void kernel_launch(void* const* d_in, const int* in_sizes, int n_in,
                              void* d_out, int out_size)
{
    const float* query = (const float*)d_in[0];
    const float* key   = (const float*)d_in[1];
    const float* value = (const float*)d_in[2];
    const int*   mask  = (const int*)d_in[3];
    const float* wq = (const float*)d_in[4];
    const float* bq = (const float*)d_in[5];
    const float* wk = (const float*)d_in[6];
    const float* bk = (const float*)d_in[7];
    const float* wv = (const float*)d_in[8];
    const float* bv = (const float*)d_in[9];
    const float* wo = (const float*)d_in[10];
    const float* bo = (const float*)d_in[11];

    float* out   = (float*)d_out;                       // [B, S, D]
    float* probs = out + (size_t)BATCH * SEQ * DM;      // [B, H, S, S]

    float *qp, *kp, *vp, *ap;
    cudaGetSymbolAddress((void**)&qp, g_q);
    cudaGetSymbolAddress((void**)&kp, g_k);
    cudaGetSymbolAddress((void**)&vp, g_v);
    cudaGetSymbolAddress((void**)&ap, g_attn);

    dim3 proj_grid(DM / 64, (BATCH * SEQ) / 128);       // (12, 32)
    proj_kernel<<<proj_grid, 256>>>(query, wq, bq, qp);
    proj_kernel<<<proj_grid, 256>>>(key,   wk, bk, kp);
    proj_kernel<<<proj_grid, 256>>>(value, wv, bv, vp);

    dim3 sc_grid(SEQ / 64, SEQ / 128, BATCH * NH);      // (32, 16, 24)
    scores_kernel<<<sc_grid, 256>>>(mask, probs);

    softmax_kernel<<<BATCH * NH * SEQ, 256>>>(probs);   // 49152 rows

    dim3 pv_grid(1, SEQ / 128, BATCH * NH);             // (1, 16, 24)
    pv_kernel<<<pv_grid, 256>>>(probs);

    proj_kernel<<<proj_grid, 256>>>(ap, wo, bo, out);
}

// round 2
// speedup vs baseline: 1.7086x; 1.7086x over previous
#include <cuda_runtime.h>
#include <cstdint>
#include <cstddef>

// Problem constants
#define BATCH 2
#define SEQ   2048
#define DM    768
#define NH    12
#define DHD   64
#define ATT_SCALE 0.125f   // 1/sqrt(64)

// Scratch (allocation-free rule: __device__ globals)
__device__ float g_q[BATCH * SEQ * DM];
__device__ float g_k[BATCH * SEQ * DM];
__device__ float g_v[BATCH * SEQ * DM];
__device__ float g_attn[BATCH * SEQ * DM];

// ---------------------------------------------------------------------------
// tf32 helpers
// ---------------------------------------------------------------------------
__device__ __forceinline__ uint32_t f2tf32(float f) {
    uint32_t u;
    asm("cvt.rna.tf32.f32 %0, %1;" : "=r"(u) : "f"(f));
    return u;
}

__device__ __forceinline__ void mma8(float* c, const uint32_t* a, const uint32_t* b) {
    asm volatile(
        "mma.sync.aligned.m16n8k8.row.col.f32.tf32.tf32.f32 "
        "{%0,%1,%2,%3},{%4,%5,%6,%7},{%8,%9},{%0,%1,%2,%3};"
        : "+f"(c[0]), "+f"(c[1]), "+f"(c[2]), "+f"(c[3])
        : "r"(a[0]), "r"(a[1]), "r"(a[2]), "r"(a[3]), "r"(b[0]), "r"(b[1]));
}

// ---------------------------------------------------------------------------
// Tensor-core block GEMM: C[128 x BN] = A[128 x K] * B[K x BN]
//   A row-major (lda between rows), pre-offset to block row.
//   BTRANS=true : B[n*ldb + k] (weights / K^T).  false: B[k*ldb + n].
// 256 threads = 8 warps laid out WMW x WNW; warp tile = (MT*16) x (NTL*8).
// BK = 16.  K % 16 == 0.  smem padded +8 -> fragment LDS conflict-free.
// ---------------------------------------------------------------------------
template <int BN, int WMW, int WNW, int MT, int NTL, bool BTRANS>
__device__ __forceinline__ void gemm_tc(
    const float* __restrict__ A, int lda,
    const float* __restrict__ B, int ldb,
    int K, float acc[MT][NTL][4])
{
    __shared__ uint32_t As[16][128 + 8];
    __shared__ uint32_t Bs[16][BN + 8];

    const int tid  = threadIdx.x;
    const int lane = tid & 31;
    const int warp = tid >> 5;
    const int wm0  = (warp % WMW) * (MT * 16);
    const int wn0  = (warp / WMW) * (NTL * 8);

    for (int k0 = 0; k0 < K; k0 += 16) {
        // A tile: 128 rows x 16 k, transpose into As[k][m]
        #pragma unroll
        for (int t = 0; t < 2; t++) {
            int i = tid + t * 256;
            int r = i >> 2;
            int c = (i & 3) * 4;
            float4 v = *(const float4*)(A + (size_t)r * lda + k0 + c);
            As[c + 0][r] = f2tf32(v.x);
            As[c + 1][r] = f2tf32(v.y);
            As[c + 2][r] = f2tf32(v.z);
            As[c + 3][r] = f2tf32(v.w);
        }
        // B tile -> Bs[k][n]
        if (BTRANS) {
            #pragma unroll
            for (int t = 0; t < BN / 64; t++) {
                int i = tid + t * 256;
                int n = i >> 2;
                int c = (i & 3) * 4;
                float4 v = *(const float4*)(B + (size_t)n * ldb + k0 + c);
                Bs[c + 0][n] = f2tf32(v.x);
                Bs[c + 1][n] = f2tf32(v.y);
                Bs[c + 2][n] = f2tf32(v.z);
                Bs[c + 3][n] = f2tf32(v.w);
            }
        } else {
            #pragma unroll
            for (int t = 0; t < BN / 64; t++) {
                int i  = tid + t * 256;
                int kk = i / (BN / 4);
                int n  = (i % (BN / 4)) * 4;
                float4 v = *(const float4*)(B + (size_t)(k0 + kk) * ldb + n);
                Bs[kk][n + 0] = f2tf32(v.x);
                Bs[kk][n + 1] = f2tf32(v.y);
                Bs[kk][n + 2] = f2tf32(v.z);
                Bs[kk][n + 3] = f2tf32(v.w);
            }
        }
        __syncthreads();

        #pragma unroll
        for (int ks = 0; ks < 16; ks += 8) {
            uint32_t af[MT][4], bf[NTL][2];
            const int kb = ks + (lane & 3);
            const int g  = lane >> 2;
            #pragma unroll
            for (int mt = 0; mt < MT; mt++) {
                int m = wm0 + mt * 16 + g;
                af[mt][0] = As[kb][m];
                af[mt][1] = As[kb][m + 8];
                af[mt][2] = As[kb + 4][m];
                af[mt][3] = As[kb + 4][m + 8];
            }
            #pragma unroll
            for (int nt = 0; nt < NTL; nt++) {
                int n = wn0 + nt * 8 + g;
                bf[nt][0] = Bs[kb][n];
                bf[nt][1] = Bs[kb + 4][n];
            }
            #pragma unroll
            for (int mt = 0; mt < MT; mt++)
                #pragma unroll
                for (int nt = 0; nt < NTL; nt++)
                    mma8(acc[mt][nt], af[mt], bf[nt]);
        }
        __syncthreads();
    }
}

// ---------------------------------------------------------------------------
// Projection: Y[M, 768] = X[M,768] @ W^T + bias.  grid = (768/128=6, M/128)
// ---------------------------------------------------------------------------
__global__ void proj_kernel(const float* __restrict__ X,
                            const float* __restrict__ W,
                            const float* __restrict__ bias,
                            float* __restrict__ Y)
{
    const int row0 = blockIdx.y * 128;
    const int col0 = blockIdx.x * 128;
    float acc[4][4][4] = {};
    gemm_tc<128, 2, 4, 4, 4, true>(X + (size_t)row0 * DM, DM,
                                   W + (size_t)col0 * DM, DM, DM, acc);

    const int lane = threadIdx.x & 31;
    const int warp = threadIdx.x >> 5;
    const int wm0 = (warp % 2) * 64, wn0 = (warp / 2) * 32;
    #pragma unroll
    for (int mt = 0; mt < 4; mt++) {
        int r = row0 + wm0 + mt * 16 + (lane >> 2);
        #pragma unroll
        for (int nt = 0; nt < 4; nt++) {
            int ccol = col0 + wn0 + nt * 8 + 2 * (lane & 3);
            float2 bv = *(const float2*)&bias[ccol];
            float2 o0 = { acc[mt][nt][0] + bv.x, acc[mt][nt][1] + bv.y };
            float2 o1 = { acc[mt][nt][2] + bv.x, acc[mt][nt][3] + bv.y };
            *(float2*)&Y[(size_t)r * DM + ccol]       = o0;
            *(float2*)&Y[(size_t)(r + 8) * DM + ccol] = o1;
        }
    }
}

// ---------------------------------------------------------------------------
// Scores: P[z,q,k] = (Q.K^T)*scale, masked.  grid = (16, 16, 24)
// ---------------------------------------------------------------------------
__global__ void scores_kernel(const int* __restrict__ mask,
                              float* __restrict__ P)
{
    const int z = blockIdx.z;
    const int b = z / NH, h = z % NH;
    const int row0 = blockIdx.y * 128;   // query
    const int col0 = blockIdx.x * 128;   // key
    float acc[4][4][4] = {};
    const float* A  = g_q + (size_t)b * SEQ * DM + h * DHD + (size_t)row0 * DM;
    const float* Bm = g_k + (size_t)b * SEQ * DM + h * DHD + (size_t)col0 * DM;
    gemm_tc<128, 2, 4, 4, 4, true>(A, DM, Bm, DM, DHD, acc);

    const int lane = threadIdx.x & 31;
    const int warp = threadIdx.x >> 5;
    const int wm0 = (warp % 2) * 64, wn0 = (warp / 2) * 32;
    const int* mrow = mask + b * SEQ;
    float* C = P + (size_t)z * SEQ * SEQ;
    #pragma unroll
    for (int nt = 0; nt < 4; nt++) {
        int ccol = col0 + wn0 + nt * 8 + 2 * (lane & 3);
        int m0 = mrow[ccol], m1 = mrow[ccol + 1];
        #pragma unroll
        for (int mt = 0; mt < 4; mt++) {
            int r = row0 + wm0 + mt * 16 + (lane >> 2);
            float2 o0, o1;
            o0.x = (m0 == 0) ? -1e9f : acc[mt][nt][0] * ATT_SCALE;
            o0.y = (m1 == 0) ? -1e9f : acc[mt][nt][1] * ATT_SCALE;
            o1.x = (m0 == 0) ? -1e9f : acc[mt][nt][2] * ATT_SCALE;
            o1.y = (m1 == 0) ? -1e9f : acc[mt][nt][3] * ATT_SCALE;
            *(float2*)&C[(size_t)r * SEQ + ccol]       = o0;
            *(float2*)&C[(size_t)(r + 8) * SEQ + ccol] = o1;
        }
    }
}

// ---------------------------------------------------------------------------
// Row softmax in place: one block per row, 256 threads x 8 elems
// ---------------------------------------------------------------------------
__global__ void softmax_kernel(float* __restrict__ P)
{
    float* row = P + (size_t)blockIdx.x * SEQ;
    const int tid = threadIdx.x;
    float v[8];
    *(float4*)&v[0] = *(const float4*)&row[tid * 8];
    *(float4*)&v[4] = *(const float4*)&row[tid * 8 + 4];

    __shared__ float warp_red[8];
    __shared__ float bcast;

    float m = v[0];
    #pragma unroll
    for (int i = 1; i < 8; i++) m = fmaxf(m, v[i]);
    #pragma unroll
    for (int o = 16; o > 0; o >>= 1) m = fmaxf(m, __shfl_xor_sync(0xffffffffu, m, o));
    if ((tid & 31) == 0) warp_red[tid >> 5] = m;
    __syncthreads();
    if (tid == 0) {
        float t = warp_red[0];
        #pragma unroll
        for (int i = 1; i < 8; i++) t = fmaxf(t, warp_red[i]);
        bcast = t;
    }
    __syncthreads();
    const float rmax = bcast;
    __syncthreads();

    float s = 0.f;
    #pragma unroll
    for (int i = 0; i < 8; i++) {
        v[i] = __expf(v[i] - rmax);
        s += v[i];
    }
    #pragma unroll
    for (int o = 16; o > 0; o >>= 1) s += __shfl_xor_sync(0xffffffffu, s, o);
    if ((tid & 31) == 0) warp_red[tid >> 5] = s;
    __syncthreads();
    if (tid == 0) {
        float t = 0.f;
        #pragma unroll
        for (int i = 0; i < 8; i++) t += warp_red[i];
        bcast = t;
    }
    __syncthreads();
    const float inv = 1.0f / bcast;

    #pragma unroll
    for (int i = 0; i < 8; i++) v[i] *= inv;
    *(float4*)&row[tid * 8]     = *(float4*)&v[0];
    *(float4*)&row[tid * 8 + 4] = *(float4*)&v[4];
}

// ---------------------------------------------------------------------------
// PV: attn[b,q,h*64+d] = sum_k P[z,q,k] * V[b,k,h*64+d].  grid = (1, 16, 24)
// ---------------------------------------------------------------------------
__global__ void pv_kernel(const float* __restrict__ P)
{
    const int z = blockIdx.z;
    const int b = z / NH, h = z % NH;
    const int row0 = blockIdx.y * 128;
    float acc[2][4][4] = {};
    const float* A  = P + (size_t)z * SEQ * SEQ + (size_t)row0 * SEQ;
    const float* Bm = g_v + (size_t)b * SEQ * DM + h * DHD;   // NN form
    gemm_tc<64, 4, 2, 2, 4, false>(A, SEQ, Bm, DM, SEQ, acc);

    const int lane = threadIdx.x & 31;
    const int warp = threadIdx.x >> 5;
    const int wm0 = (warp % 4) * 32, wn0 = (warp / 4) * 32;
    float* C = g_attn + (size_t)b * SEQ * DM + h * DHD + (size_t)row0 * DM;
    #pragma unroll
    for (int mt = 0; mt < 2; mt++) {
        int r = wm0 + mt * 16 + (lane >> 2);
        #pragma unroll
        for (int nt = 0; nt < 4; nt++) {
            int ccol = wn0 + nt * 8 + 2 * (lane & 3);
            float2 o0 = { acc[mt][nt][0], acc[mt][nt][1] };
            float2 o1 = { acc[mt][nt][2], acc[mt][nt][3] };
            *(float2*)&C[(size_t)r * DM + ccol]       = o0;
            *(float2*)&C[(size_t)(r + 8) * DM + ccol] = o1;
        }
    }
}

// ---------------------------------------------------------------------------
extern "C" void kernel_launch(void* const* d_in, const int* in_sizes, int n_in,
                              void* d_out, int out_size)
{
    const float* query = (const float*)d_in[0];
    const float* key   = (const float*)d_in[1];
    const float* value = (const float*)d_in[2];
    const int*   mask  = (const int*)d_in[3];
    const float* wq = (const float*)d_in[4];
    const float* bq = (const float*)d_in[5];
    const float* wk = (const float*)d_in[6];
    const float* bk = (const float*)d_in[7];
    const float* wv = (const float*)d_in[8];
    const float* bv = (const float*)d_in[9];
    const float* wo = (const float*)d_in[10];
    const float* bo = (const float*)d_in[11];

    float* out   = (float*)d_out;                       // [B, S, D]
    float* probs = out + (size_t)BATCH * SEQ * DM;      // [B, H, S, S]

    float *qp, *kp, *vp, *ap;
    cudaGetSymbolAddress((void**)&qp, g_q);
    cudaGetSymbolAddress((void**)&kp, g_k);
    cudaGetSymbolAddress((void**)&vp, g_v);
    cudaGetSymbolAddress((void**)&ap, g_attn);

    dim3 proj_grid(DM / 128, (BATCH * SEQ) / 128);      // (6, 32)
    proj_kernel<<<proj_grid, 256>>>(query, wq, bq, qp);
    proj_kernel<<<proj_grid, 256>>>(key,   wk, bk, kp);
    proj_kernel<<<proj_grid, 256>>>(value, wv, bv, vp);

    dim3 sc_grid(SEQ / 128, SEQ / 128, BATCH * NH);     // (16, 16, 24)
    scores_kernel<<<sc_grid, 256>>>(mask, probs);

    softmax_kernel<<<BATCH * NH * SEQ, 256>>>(probs);   // 49152 rows

    dim3 pv_grid(1, SEQ / 128, BATCH * NH);             // (1, 16, 24)
    pv_kernel<<<pv_grid, 256>>>(probs);

    proj_kernel<<<proj_grid, 256>>>(ap, wo, bo, out);
}